// round 9
// baseline (speedup 1.0000x reference)
#include <cuda_runtime.h>
#include <cuda_bf16.h>
#include <cstdint>

#define N_NODES_MAX 100000
#define E_MAX       1600000
#define K_DIM       256
#define H_DIM       128
#define SCAN_B      1024
#define NB_MAX      ((N_NODES_MAX + SCAN_B - 1) / SCAN_B)   // 98

typedef unsigned long long ull;

// packed fp32x2 FMA (Blackwell FFMA2 — PTX-only, ptxas won't auto-fuse)
#define FMA2(d, a, b, c) \
    asm("fma.rn.f32x2 %0, %1, %2, %3;" : "=l"(d) : "l"(a), "l"(b), "l"(c))
#define PACKDUP(d, f) \
    asm("mov.b64 %0, {%1, %1};" : "=l"(d) : "f"(f))
#define UNPACK2(lo, hi, p) \
    asm("mov.b64 {%0, %1}, %2;" : "=f"(lo), "=f"(hi) : "l"(p))

// ---------------- device scratch (static, no allocation) ----------------
__device__ float  g_h[(size_t)N_NODES_MAX * H_DIM];   // h = x@W (UNSCALED)
__device__ int    g_count[N_NODES_MAX];
__device__ int    g_off[N_NODES_MAX + 1];
__device__ int    g_cursor[N_NODES_MAX];
__device__ float  g_dinv[N_NODES_MAX];
__device__ float2 g_srcd[E_MAX];                      // {bitcast src, dinv[src]}
__device__ int    g_bsum[NB_MAX + 1];
__device__ int    g_is64;
__device__ int    g_swap;

// ---------------- probe: dtype of edge buffer + b/alpha order ----------------
__global__ void detect_kernel(const int* __restrict__ e,
                              const float* __restrict__ pb,
                              const float* __restrict__ pa) {
    int lane = threadIdx.x & 31;
    int nz = (e[2 * lane + 1] != 0) ? 1 : 0;     // odd words zero <=> int64
    unsigned m = __ballot_sync(0xFFFFFFFFu, nz);
    if (lane == 0) {
        g_is64 = (m == 0u) ? 1 : 0;
        g_swap = (pb[0] != 0.0f && pa[0] == 0.0f) ? 1 : 0;
    }
}

// ---------------- build CSR-by-destination ----------------
__global__ void zero_count_kernel(int n) {
    int i = blockIdx.x * blockDim.x + threadIdx.x;
    if (i < n) g_count[i] = 0;
}

// 4 destinations per thread, vectorized loads for both dtype layouts
__global__ void hist_kernel(const int* __restrict__ e, int E, int N) {
    int base = (blockIdx.x * blockDim.x + threadIdx.x) * 4;
    if (base >= E) return;
    int c[4];
    if (base + 3 < E) {
        if (g_is64) {
            const int* p = e + 2 * (long long)E + 2 * (long long)base;
            int4 w0 = *(const int4*)(p);
            int4 w1 = *(const int4*)(p + 4);
            c[0] = w0.x; c[1] = w0.z; c[2] = w1.x; c[3] = w1.z;
        } else {
            int4 w = *(const int4*)(e + (long long)E + base);
            c[0] = w.x; c[1] = w.y; c[2] = w.z; c[3] = w.w;
        }
#pragma unroll
        for (int j = 0; j < 4; j++)
            if ((unsigned)c[j] < (unsigned)N) atomicAdd(&g_count[c[j]], 1);
    } else {
        for (int j = 0; base + j < E; j++) {
            long long idx = (long long)E + base + j;
            int cc = g_is64 ? e[2 * idx] : e[idx];
            if ((unsigned)cc < (unsigned)N) atomicAdd(&g_count[cc], 1);
        }
    }
}

__global__ __launch_bounds__(SCAN_B) void scanA_kernel(int N) {
    __shared__ int sm[SCAN_B];
    const int tid = threadIdx.x;
    const int i = blockIdx.x * SCAN_B + tid;
    int v = (i < N) ? g_count[i] : 0;
    sm[tid] = v;
    __syncthreads();
#pragma unroll
    for (int d = 1; d < SCAN_B; d <<= 1) {
        int t = sm[tid];
        int add = (tid >= d) ? sm[tid - d] : 0;
        __syncthreads();
        sm[tid] = t + add;
        __syncthreads();
    }
    if (i < N) g_off[i] = sm[tid] - v;
    if (tid == SCAN_B - 1) g_bsum[blockIdx.x] = sm[tid];
}

__global__ void scanB_kernel(int nb) {
    __shared__ int sm[128];
    const int tid = threadIdx.x;
    int v = (tid < nb) ? g_bsum[tid] : 0;
    sm[tid] = v;
    __syncthreads();
#pragma unroll
    for (int d = 1; d < 128; d <<= 1) {
        int t = sm[tid];
        int add = (tid >= d) ? sm[tid - d] : 0;
        __syncthreads();
        sm[tid] = t + add;
        __syncthreads();
    }
    if (tid < nb) g_bsum[tid] = sm[tid] - v;
}

__global__ void scanC_kernel(int N) {
    int i = blockIdx.x * blockDim.x + threadIdx.x;
    if (i >= N) return;
    int cnt = g_count[i];
    int off = g_off[i] + g_bsum[i >> 10];
    g_off[i] = off;
    g_cursor[i] = off;
    g_dinv[i] = rsqrtf((float)cnt + 1.0f);
    if (i == N - 1) g_off[N] = off + cnt;
}

// 4 edges per thread; emits packed {src, dinv[src]} records
__global__ void scatter_src_kernel(const int* __restrict__ e, int E, int N) {
    int base = (blockIdx.x * blockDim.x + threadIdx.x) * 4;
    if (base >= E) return;
    int r[4], c[4];
    int n = 4;
    if (base + 3 < E) {
        if (g_is64) {
            const int* pr = e + 2 * (long long)base;
            const int* pc = e + 2 * (long long)E + 2 * (long long)base;
            int4 r0 = *(const int4*)(pr);
            int4 r1 = *(const int4*)(pr + 4);
            int4 c0 = *(const int4*)(pc);
            int4 c1 = *(const int4*)(pc + 4);
            r[0] = r0.x; r[1] = r0.z; r[2] = r1.x; r[3] = r1.z;
            c[0] = c0.x; c[1] = c0.z; c[2] = c1.x; c[3] = c1.z;
        } else {
            int4 rv = *(const int4*)(e + base);
            int4 cv = *(const int4*)(e + (long long)E + base);
            r[0] = rv.x; r[1] = rv.y; r[2] = rv.z; r[3] = rv.w;
            c[0] = cv.x; c[1] = cv.y; c[2] = cv.z; c[3] = cv.w;
        }
    } else {
        n = E - base;
        for (int j = 0; j < n; j++) {
            long long ir = (long long)base + j;
            long long ic = (long long)E + base + j;
            r[j] = g_is64 ? e[2 * ir] : e[ir];
            c[j] = g_is64 ? e[2 * ic] : e[ic];
        }
    }
#pragma unroll
    for (int j = 0; j < 4; j++) {
        if (j >= n) break;
        if ((unsigned)r[j] < (unsigned)N && (unsigned)c[j] < (unsigned)N) {
            float dv = g_dinv[r[j]];
            int p = atomicAdd(&g_cursor[c[j]], 1);
            if ((unsigned)p < (unsigned)E_MAX)
                g_srcd[p] = make_float2(__int_as_float(r[j]), dv);
        }
    }
}

// ---------------- SGEMM: g_h = x @ W (raw, FFMA2 inner loop) ----------------
#define BM 128
#define BN 128
#define BK 16
__global__ __launch_bounds__(256) void gemm_kernel(const float* __restrict__ A,
                                                   const float* __restrict__ B,
                                                   int M) {
    __shared__ float As[BK][BM + 4];
    __shared__ float Bs[BK][BN + 4];
    const int tid = threadIdx.x;
    const int brow = blockIdx.x * BM;
    const int tr = tid >> 4;
    const int tc = tid & 15;

    ull accp[8][4];
#pragma unroll
    for (int i = 0; i < 8; i++)
#pragma unroll
        for (int j = 0; j < 4; j++) accp[i][j] = 0ULL;

    for (int kt = 0; kt < K_DIM; kt += BK) {
#pragma unroll
        for (int t = 0; t < 2; t++) {
            int v = tid + t * 256;
            int r = v >> 2;
            int kc = (v & 3) * 4;
            float4 a;
            int grow = brow + r;
            if (grow < M) a = *(const float4*)(A + (size_t)grow * K_DIM + kt + kc);
            else a = make_float4(0.f, 0.f, 0.f, 0.f);
            As[kc + 0][r] = a.x; As[kc + 1][r] = a.y;
            As[kc + 2][r] = a.z; As[kc + 3][r] = a.w;
        }
#pragma unroll
        for (int t = 0; t < 2; t++) {
            int v = tid + t * 256;
            int r = v >> 5;
            int col = (v & 31) * 4;
            float4 bv = *(const float4*)(B + (size_t)(kt + r) * BN + col);
            *(float4*)(&Bs[r][col]) = bv;
        }
        __syncthreads();
#pragma unroll
        for (int k = 0; k < BK; k++) {
            float ra[8];
            *(float4*)&ra[0] = *(const float4*)&As[k][tr * 4];
            *(float4*)&ra[4] = *(const float4*)&As[k][tr * 4 + 64];
            ull rbp[4];
            {
                const ull* p0 = (const ull*)&Bs[k][tc * 4];
                const ull* p1 = (const ull*)&Bs[k][tc * 4 + 64];
                rbp[0] = p0[0]; rbp[1] = p0[1];
                rbp[2] = p1[0]; rbp[3] = p1[1];
            }
#pragma unroll
            for (int i = 0; i < 8; i++) {
                ull rap;
                PACKDUP(rap, ra[i]);
                FMA2(accp[i][0], rap, rbp[0], accp[i][0]);
                FMA2(accp[i][1], rap, rbp[1], accp[i][1]);
                FMA2(accp[i][2], rap, rbp[2], accp[i][2]);
                FMA2(accp[i][3], rap, rbp[3], accp[i][3]);
            }
        }
        __syncthreads();
    }
#pragma unroll
    for (int i = 0; i < 8; i++) {
        int r = brow + tr * 4 + ((i < 4) ? i : (64 + i - 4));
        if (r < M) {
            float4 o0, o1;
            UNPACK2(o0.x, o0.y, accp[i][0]);
            UNPACK2(o0.z, o0.w, accp[i][1]);
            UNPACK2(o1.x, o1.y, accp[i][2]);
            UNPACK2(o1.z, o1.w, accp[i][3]);
            *(float4*)(g_h + (size_t)r * H_DIM + tc * 4) = o0;
            *(float4*)(g_h + (size_t)r * H_DIM + tc * 4 + 64) = o1;
        }
    }
}

// ---------------- gather + bias + PReLU (packed src records, unroll 8) -------
__global__ __launch_bounds__(256) void gather_kernel(const float* __restrict__ pb,
                                                     const float* __restrict__ pa,
                                                     float* __restrict__ out, int N) {
    int warp = (blockIdx.x * blockDim.x + threadIdx.x) >> 5;
    int lane = threadIdx.x & 31;
    if (warp >= N) return;
    const int c = warp;
    const float dc = g_dinv[c];
    const int s = g_off[c];
    const int e = g_off[c + 1];

    // self-loop: h[c] * dinv[c]   (whole sum gets * dc at the end)
    float4 hc = *(const float4*)(g_h + (size_t)c * H_DIM + lane * 4);
    float4 acc;
    acc.x = hc.x * dc; acc.y = hc.y * dc; acc.z = hc.z * dc; acc.w = hc.w * dc;

    int i = s;
    for (; i + 7 < e; i += 8) {
        float2 p[8];
#pragma unroll
        for (int j = 0; j < 8; j++) p[j] = g_srcd[i + j];
        float4 v[8];
#pragma unroll
        for (int j = 0; j < 8; j++) {
            int sj = __float_as_int(p[j].x);
            v[j] = *(const float4*)(g_h + (size_t)sj * H_DIM + lane * 4);
        }
#pragma unroll
        for (int j = 0; j < 8; j++) {
            float dj = p[j].y;
            acc.x = fmaf(v[j].x, dj, acc.x);
            acc.y = fmaf(v[j].y, dj, acc.y);
            acc.z = fmaf(v[j].z, dj, acc.z);
            acc.w = fmaf(v[j].w, dj, acc.w);
        }
    }
    for (; i < e; i++) {
        float2 p0 = g_srcd[i];
        int s0 = __float_as_int(p0.x);
        float d0 = p0.y;
        float4 v0 = *(const float4*)(g_h + (size_t)s0 * H_DIM + lane * 4);
        acc.x = fmaf(v0.x, d0, acc.x);
        acc.y = fmaf(v0.y, d0, acc.y);
        acc.z = fmaf(v0.z, d0, acc.z);
        acc.w = fmaf(v0.w, d0, acc.w);
    }

    float4 bb = *(const float4*)(pb + lane * 4);
    float4 aa = *(const float4*)(pa + lane * 4);
    if (g_swap) { float4 t = bb; bb = aa; aa = t; }
    float4 r;
    float t;
    t = fmaf(acc.x, dc, bb.x); r.x = (t >= 0.f) ? t : aa.x * t;
    t = fmaf(acc.y, dc, bb.y); r.y = (t >= 0.f) ? t : aa.y * t;
    t = fmaf(acc.z, dc, bb.z); r.z = (t >= 0.f) ? t : aa.z * t;
    t = fmaf(acc.w, dc, bb.w); r.w = (t >= 0.f) ? t : aa.w * t;
    *(float4*)(out + (size_t)c * H_DIM + lane * 4) = r;
}

// ---------------- launch (fork-join: GEMM overlaps edge ingestion) ----------------
extern "C" void kernel_launch(void* const* d_in, const int* in_sizes, int n_in,
                              void* d_out, int out_size) {
    int ix = -1, ie = -1, iw = -1;
    for (int pass = 0; pass < 3; pass++) {
        int best = -1;
        long long bs = -1;
        for (int i = 0; i < n_in; i++) {
            if (i == ix || i == ie || i == iw) continue;
            if ((long long)in_sizes[i] > bs) { bs = in_sizes[i]; best = i; }
        }
        if (pass == 0) ix = best; else if (pass == 1) ie = best; else iw = best;
    }
    int ib = -1, ia = -1;
    for (int i = 0; i < n_in; i++) {
        if (i == ix || i == ie || i == iw) continue;
        if (ib < 0) ib = i; else ia = i;
    }

    const float* x = (const float*)d_in[ix];
    const int*   e = (const int*)d_in[ie];
    const float* W = (const float*)d_in[iw];
    const float* b = (const float*)d_in[ib];
    const float* alpha = (const float*)d_in[ia];
    float* out = (float*)d_out;

    const int N = in_sizes[ix] / K_DIM;   // 100000
    const int E = in_sizes[ie] / 2;       // 1600000
    const int NB = (N + SCAN_B - 1) / SCAN_B;
    const int TB = 256;
    const int E4 = (E + 3) / 4;           // threads for 4-edge kernels

    static cudaStream_t s2 = nullptr;
    static cudaEvent_t evFork = nullptr, evJoin = nullptr;
    if (s2 == nullptr) {
        cudaStreamCreateWithFlags(&s2, cudaStreamNonBlocking);
        cudaEventCreateWithFlags(&evFork, cudaEventDisableTiming);
        cudaEventCreateWithFlags(&evJoin, cudaEventDisableTiming);
    }

    // fork: GEMM on s2 (depends on nothing device-side)
    cudaEventRecord(evFork, 0);
    cudaStreamWaitEvent(s2, evFork, 0);
    gemm_kernel<<<(N + BM - 1) / BM, 256, 0, s2>>>(x, W, N);
    cudaEventRecord(evJoin, s2);

    // edge ingestion chain on main stream
    detect_kernel<<<1, 32>>>(e, b, alpha);
    zero_count_kernel<<<(N + TB - 1) / TB, TB>>>(N);
    hist_kernel<<<(E4 + TB - 1) / TB, TB>>>(e, E, N);
    scanA_kernel<<<NB, SCAN_B>>>(N);
    scanB_kernel<<<1, 128>>>(NB);
    scanC_kernel<<<(N + TB - 1) / TB, TB>>>(N);
    scatter_src_kernel<<<(E4 + TB - 1) / TB, TB>>>(e, E, N);

    // join, then gather
    cudaStreamWaitEvent(0, evJoin, 0);
    gather_kernel<<<(int)(((long long)N * 32 + TB - 1) / TB), TB>>>(b, alpha, out, N);
}

// round 11
// speedup vs baseline: 1.3964x; 1.3964x over previous
#include <cuda_runtime.h>
#include <cuda_bf16.h>
#include <cstdint>

#define N_NODES_MAX 100000
#define E_MAX       1600000
#define K_DIM       256
#define H_DIM       128
#define SCAN_B      1024
#define NB_MAX      ((N_NODES_MAX + SCAN_B - 1) / SCAN_B)   // 98

// ---------------- device scratch (static, no allocation) ----------------
__device__ float g_h[(size_t)N_NODES_MAX * H_DIM];   // h = x@W (UNSCALED)
__device__ int   g_count[N_NODES_MAX];
__device__ int   g_off[N_NODES_MAX + 1];
__device__ int   g_cursor[N_NODES_MAX];
__device__ float g_dinv[N_NODES_MAX];
__device__ int   g_src[E_MAX];
__device__ int   g_bsum[NB_MAX + 1];
__device__ int   g_is64;
__device__ int   g_swap;

// ---------------- probe: dtype of edge buffer + b/alpha order ----------------
__global__ void detect_kernel(const int* __restrict__ e,
                              const float* __restrict__ pb,
                              const float* __restrict__ pa) {
    int lane = threadIdx.x & 31;
    int nz = (e[2 * lane + 1] != 0) ? 1 : 0;     // odd words zero <=> int64
    unsigned m = __ballot_sync(0xFFFFFFFFu, nz);
    if (lane == 0) {
        g_is64 = (m == 0u) ? 1 : 0;
        g_swap = (pb[0] != 0.0f && pa[0] == 0.0f) ? 1 : 0;
    }
}

__device__ __forceinline__ int edge_val(const int* e, long long idx) {
    return g_is64 ? e[2 * idx] : e[(size_t)idx];
}

// ---------------- build CSR-by-destination ----------------
__global__ void zero_count_kernel(int n) {
    int i = blockIdx.x * blockDim.x + threadIdx.x;
    if (i < n) g_count[i] = 0;
}

__global__ void hist_kernel(const int* __restrict__ e, int E, int N) {
    int i = blockIdx.x * blockDim.x + threadIdx.x;
    if (i >= E) return;
    unsigned c = (unsigned)edge_val(e, (long long)E + i);
    if (c < (unsigned)N) atomicAdd(&g_count[c], 1);
}

__global__ __launch_bounds__(SCAN_B) void scanA_kernel(int N) {
    __shared__ int sm[SCAN_B];
    const int tid = threadIdx.x;
    const int i = blockIdx.x * SCAN_B + tid;
    int v = (i < N) ? g_count[i] : 0;
    sm[tid] = v;
    __syncthreads();
#pragma unroll
    for (int d = 1; d < SCAN_B; d <<= 1) {
        int t = sm[tid];
        int add = (tid >= d) ? sm[tid - d] : 0;
        __syncthreads();
        sm[tid] = t + add;
        __syncthreads();
    }
    if (i < N) g_off[i] = sm[tid] - v;
    if (tid == SCAN_B - 1) g_bsum[blockIdx.x] = sm[tid];
}

__global__ void scanB_kernel(int nb) {
    __shared__ int sm[128];
    const int tid = threadIdx.x;
    int v = (tid < nb) ? g_bsum[tid] : 0;
    sm[tid] = v;
    __syncthreads();
#pragma unroll
    for (int d = 1; d < 128; d <<= 1) {
        int t = sm[tid];
        int add = (tid >= d) ? sm[tid - d] : 0;
        __syncthreads();
        sm[tid] = t + add;
        __syncthreads();
    }
    if (tid < nb) g_bsum[tid] = sm[tid] - v;
}

__global__ void scanC_kernel(int N) {
    int i = blockIdx.x * blockDim.x + threadIdx.x;
    if (i >= N) return;
    int cnt = g_count[i];
    int off = g_off[i] + g_bsum[i >> 10];
    g_off[i] = off;
    g_cursor[i] = off;
    g_dinv[i] = rsqrtf((float)cnt + 1.0f);
    if (i == N - 1) g_off[N] = off + cnt;
}

__global__ void scatter_src_kernel(const int* __restrict__ e, int E, int N) {
    int i = blockIdx.x * blockDim.x + threadIdx.x;
    if (i >= E) return;
    unsigned r = (unsigned)edge_val(e, i);
    unsigned c = (unsigned)edge_val(e, (long long)E + i);
    if (r < (unsigned)N && c < (unsigned)N) {
        int p = atomicAdd(&g_cursor[c], 1);
        if ((unsigned)p < (unsigned)E) g_src[p] = (int)r;
    }
}

// ---------------- tf32 tensor-core GEMM: g_h = x @ W ----------------
// CTA 128x128, 8 warps (4M x 2N), warp tile 32x64, k-slice 16, double buffer.
#define BM 128
#define BN 128
#define BKT 16
#define SMP (BM + 8)   // padded stride: bank = 8*tig + gid -> conflict-free

__device__ __forceinline__ uint32_t f2tf(float f) {
    uint32_t u;
    asm("cvt.rna.tf32.f32 %0, %1;" : "=r"(u) : "f"(f));
    return u;
}

__global__ __launch_bounds__(256) void gemm_tf32_kernel(const float* __restrict__ A,
                                                        const float* __restrict__ Bw,
                                                        int M) {
    __shared__ uint32_t As[2][BKT][SMP];   // [buf][k][m]
    __shared__ uint32_t Bs[2][BKT][SMP];   // [buf][k][n]
    const int tid = threadIdx.x;
    const int brow = blockIdx.x * BM;
    const int wid = tid >> 5;
    const int lane = tid & 31;
    const int gid = lane >> 2;       // 0..7
    const int tig = lane & 3;        // 0..3
    const int mrow0 = (wid & 3) * 32;
    const int ncol0 = (wid >> 2) * 64;

    float acc[2][8][4];
#pragma unroll
    for (int mt = 0; mt < 2; mt++)
#pragma unroll
        for (int nt = 0; nt < 8; nt++)
#pragma unroll
            for (int q = 0; q < 4; q++) acc[mt][nt][q] = 0.0f;

    // ---- stage slice 0 into buffer 0 ----
#pragma unroll
    for (int t = 0; t < 2; t++) {
        int v = tid + t * 256;
        int r = v >> 2;              // 0..127 (m)
        int kc = (v & 3) * 4;        // 0,4,8,12 (k)
        int grow = brow + r;
        float4 a = (grow < M) ? *(const float4*)(A + (size_t)grow * K_DIM + kc)
                              : make_float4(0.f, 0.f, 0.f, 0.f);
        As[0][kc + 0][r] = f2tf(a.x);
        As[0][kc + 1][r] = f2tf(a.y);
        As[0][kc + 2][r] = f2tf(a.z);
        As[0][kc + 3][r] = f2tf(a.w);
    }
#pragma unroll
    for (int t = 0; t < 2; t++) {
        int v = tid + t * 256;
        int r = v >> 5;              // 0..15 (k)
        int c = (v & 31) * 4;        // 0..124 (n)
        float4 b = *(const float4*)(Bw + (size_t)r * BN + c);
        Bs[0][r][c + 0] = f2tf(b.x);
        Bs[0][r][c + 1] = f2tf(b.y);
        Bs[0][r][c + 2] = f2tf(b.z);
        Bs[0][r][c + 3] = f2tf(b.w);
    }
    __syncthreads();

    const int NS = K_DIM / BKT;      // 16
    for (int kt = 0; kt < NS; kt++) {
        const int cur = kt & 1;
        const int nxt = cur ^ 1;

        // prefetch next slice into registers
        float4 pa[2], pb[2];
        if (kt + 1 < NS) {
            int kbase = (kt + 1) * BKT;
#pragma unroll
            for (int t = 0; t < 2; t++) {
                int v = tid + t * 256;
                int r = v >> 2;
                int kc = (v & 3) * 4;
                int grow = brow + r;
                pa[t] = (grow < M)
                    ? *(const float4*)(A + (size_t)grow * K_DIM + kbase + kc)
                    : make_float4(0.f, 0.f, 0.f, 0.f);
                int rb = v >> 5;
                int cb = (v & 31) * 4;
                pb[t] = *(const float4*)(Bw + (size_t)(kbase + rb) * BN + cb);
            }
        }

        // compute: two k8 halves of this 16-wide slice
#pragma unroll
        for (int kh = 0; kh < 2; kh++) {
            const int k0 = kh * 8;
            uint32_t bfr[8][2];
#pragma unroll
            for (int nt = 0; nt < 8; nt++) {
                bfr[nt][0] = Bs[cur][k0 + tig][ncol0 + nt * 8 + gid];
                bfr[nt][1] = Bs[cur][k0 + tig + 4][ncol0 + nt * 8 + gid];
            }
#pragma unroll
            for (int mt = 0; mt < 2; mt++) {
                const int mb = mrow0 + mt * 16;
                uint32_t a0 = As[cur][k0 + tig][mb + gid];
                uint32_t a1 = As[cur][k0 + tig][mb + gid + 8];
                uint32_t a2 = As[cur][k0 + tig + 4][mb + gid];
                uint32_t a3 = As[cur][k0 + tig + 4][mb + gid + 8];
#pragma unroll
                for (int nt = 0; nt < 8; nt++) {
                    asm volatile(
                        "mma.sync.aligned.m16n8k8.row.col.f32.tf32.tf32.f32 "
                        "{%0,%1,%2,%3}, {%4,%5,%6,%7}, {%8,%9}, {%0,%1,%2,%3};"
                        : "+f"(acc[mt][nt][0]), "+f"(acc[mt][nt][1]),
                          "+f"(acc[mt][nt][2]), "+f"(acc[mt][nt][3])
                        : "r"(a0), "r"(a1), "r"(a2), "r"(a3),
                          "r"(bfr[nt][0]), "r"(bfr[nt][1]));
                }
            }
        }

        if (kt + 1 < NS) {
            __syncthreads();   // all warps done computing before overwrite
#pragma unroll
            for (int t = 0; t < 2; t++) {
                int v = tid + t * 256;
                int r = v >> 2;
                int kc = (v & 3) * 4;
                As[nxt][kc + 0][r] = f2tf(pa[t].x);
                As[nxt][kc + 1][r] = f2tf(pa[t].y);
                As[nxt][kc + 2][r] = f2tf(pa[t].z);
                As[nxt][kc + 3][r] = f2tf(pa[t].w);
                int rb = v >> 5;
                int cb = (v & 31) * 4;
                Bs[nxt][rb][cb + 0] = f2tf(pb[t].x);
                Bs[nxt][rb][cb + 1] = f2tf(pb[t].y);
                Bs[nxt][rb][cb + 2] = f2tf(pb[t].z);
                Bs[nxt][rb][cb + 3] = f2tf(pb[t].w);
            }
            __syncthreads();   // stores visible before next iteration reads
        }
    }

    // ---- epilogue: store fp32 h ----
#pragma unroll
    for (int mt = 0; mt < 2; mt++) {
#pragma unroll
        for (int nt = 0; nt < 8; nt++) {
            int r0 = brow + mrow0 + mt * 16 + gid;
            int col = ncol0 + nt * 8 + 2 * tig;
            if (r0 < M) {
                float2 v0 = make_float2(acc[mt][nt][0], acc[mt][nt][1]);
                *(float2*)(g_h + (size_t)r0 * H_DIM + col) = v0;
            }
            if (r0 + 8 < M) {
                float2 v1 = make_float2(acc[mt][nt][2], acc[mt][nt][3]);
                *(float2*)(g_h + (size_t)(r0 + 8) * H_DIM + col) = v1;
            }
        }
    }
}

// ---------------- gather + per-src dinv + bias + PReLU ----------------
__global__ __launch_bounds__(256) void gather_kernel(const float* __restrict__ pb,
                                                     const float* __restrict__ pa,
                                                     float* __restrict__ out, int N) {
    int warp = (blockIdx.x * blockDim.x + threadIdx.x) >> 5;
    int lane = threadIdx.x & 31;
    if (warp >= N) return;
    const int c = warp;
    const float dc = g_dinv[c];
    const int s = g_off[c];
    const int e = g_off[c + 1];

    // self-loop: h[c] * dinv[c]   (whole sum gets * dc at the end)
    float4 hc = *(const float4*)(g_h + (size_t)c * H_DIM + lane * 4);
    float4 acc;
    acc.x = hc.x * dc; acc.y = hc.y * dc; acc.z = hc.z * dc; acc.w = hc.w * dc;

    int i = s;
    for (; i + 3 < e; i += 4) {
        int s0 = g_src[i];
        int s1 = g_src[i + 1];
        int s2 = g_src[i + 2];
        int s3 = g_src[i + 3];
        float d0 = g_dinv[s0];
        float d1 = g_dinv[s1];
        float d2 = g_dinv[s2];
        float d3 = g_dinv[s3];
        float4 v0 = *(const float4*)(g_h + (size_t)s0 * H_DIM + lane * 4);
        float4 v1 = *(const float4*)(g_h + (size_t)s1 * H_DIM + lane * 4);
        float4 v2 = *(const float4*)(g_h + (size_t)s2 * H_DIM + lane * 4);
        float4 v3 = *(const float4*)(g_h + (size_t)s3 * H_DIM + lane * 4);
        acc.x = fmaf(v0.x, d0, fmaf(v1.x, d1, fmaf(v2.x, d2, fmaf(v3.x, d3, acc.x))));
        acc.y = fmaf(v0.y, d0, fmaf(v1.y, d1, fmaf(v2.y, d2, fmaf(v3.y, d3, acc.y))));
        acc.z = fmaf(v0.z, d0, fmaf(v1.z, d1, fmaf(v2.z, d2, fmaf(v3.z, d3, acc.z))));
        acc.w = fmaf(v0.w, d0, fmaf(v1.w, d1, fmaf(v2.w, d2, fmaf(v3.w, d3, acc.w))));
    }
    for (; i < e; i++) {
        int s0 = g_src[i];
        float d0 = g_dinv[s0];
        float4 v0 = *(const float4*)(g_h + (size_t)s0 * H_DIM + lane * 4);
        acc.x = fmaf(v0.x, d0, acc.x);
        acc.y = fmaf(v0.y, d0, acc.y);
        acc.z = fmaf(v0.z, d0, acc.z);
        acc.w = fmaf(v0.w, d0, acc.w);
    }

    float4 bb = *(const float4*)(pb + lane * 4);
    float4 aa = *(const float4*)(pa + lane * 4);
    if (g_swap) { float4 t = bb; bb = aa; aa = t; }
    float4 r;
    float t;
    t = fmaf(acc.x, dc, bb.x); r.x = (t >= 0.f) ? t : aa.x * t;
    t = fmaf(acc.y, dc, bb.y); r.y = (t >= 0.f) ? t : aa.y * t;
    t = fmaf(acc.z, dc, bb.z); r.z = (t >= 0.f) ? t : aa.z * t;
    t = fmaf(acc.w, dc, bb.w); r.w = (t >= 0.f) ? t : aa.w * t;
    *(float4*)(out + (size_t)c * H_DIM + lane * 4) = r;
}

// ---------------- launch (fork-join: GEMM overlaps edge ingestion) ----------------
extern "C" void kernel_launch(void* const* d_in, const int* in_sizes, int n_in,
                              void* d_out, int out_size) {
    int ix = -1, ie = -1, iw = -1;
    for (int pass = 0; pass < 3; pass++) {
        int best = -1;
        long long bs = -1;
        for (int i = 0; i < n_in; i++) {
            if (i == ix || i == ie || i == iw) continue;
            if ((long long)in_sizes[i] > bs) { bs = in_sizes[i]; best = i; }
        }
        if (pass == 0) ix = best; else if (pass == 1) ie = best; else iw = best;
    }
    int ib = -1, ia = -1;
    for (int i = 0; i < n_in; i++) {
        if (i == ix || i == ie || i == iw) continue;
        if (ib < 0) ib = i; else ia = i;
    }

    const float* x = (const float*)d_in[ix];
    const int*   e = (const int*)d_in[ie];
    const float* W = (const float*)d_in[iw];
    const float* b = (const float*)d_in[ib];
    const float* alpha = (const float*)d_in[ia];
    float* out = (float*)d_out;

    const int N = in_sizes[ix] / K_DIM;   // 100000
    const int E = in_sizes[ie] / 2;       // 1600000
    const int NB = (N + SCAN_B - 1) / SCAN_B;
    const int TB = 256;

    static cudaStream_t s2 = nullptr;
    static cudaEvent_t evFork = nullptr, evJoin = nullptr;
    if (s2 == nullptr) {
        cudaStreamCreateWithFlags(&s2, cudaStreamNonBlocking);
        cudaEventCreateWithFlags(&evFork, cudaEventDisableTiming);
        cudaEventCreateWithFlags(&evJoin, cudaEventDisableTiming);
    }

    // fork: GEMM on s2 (depends on nothing device-side)
    cudaEventRecord(evFork, 0);
    cudaStreamWaitEvent(s2, evFork, 0);
    gemm_tf32_kernel<<<(N + BM - 1) / BM, 256, 0, s2>>>(x, W, N);
    cudaEventRecord(evJoin, s2);

    // edge ingestion chain on main stream
    detect_kernel<<<1, 32>>>(e, b, alpha);
    zero_count_kernel<<<(N + TB - 1) / TB, TB>>>(N);
    hist_kernel<<<(E + TB - 1) / TB, TB>>>(e, E, N);
    scanA_kernel<<<NB, SCAN_B>>>(N);
    scanB_kernel<<<1, 128>>>(NB);
    scanC_kernel<<<(N + TB - 1) / TB, TB>>>(N);
    scatter_src_kernel<<<(E + TB - 1) / TB, TB>>>(e, E, N);

    // join, then gather
    cudaStreamWaitEvent(0, evJoin, 0);
    gather_kernel<<<(int)(((long long)N * 32 + TB - 1) / TB), TB>>>(b, alpha, out, N);
}

// round 12
// speedup vs baseline: 1.4467x; 1.0361x over previous
#include <cuda_runtime.h>
#include <cuda_fp16.h>
#include <cuda_bf16.h>
#include <cstdint>

#define N_NODES_MAX 100000
#define E_MAX       1600000
#define K_DIM       256
#define H_DIM       128
#define SCAN_B      1024
#define NB_MAX      ((N_NODES_MAX + SCAN_B - 1) / SCAN_B)   // 98

// ---------------- device scratch (static, no allocation) ----------------
__device__ __half g_h[(size_t)N_NODES_MAX * H_DIM];  // h = x@W (UNSCALED, fp16)
__device__ int    g_count[N_NODES_MAX];
__device__ int    g_off[N_NODES_MAX + 1];
__device__ int    g_cursor[N_NODES_MAX];
__device__ float  g_dinv[N_NODES_MAX];
__device__ int    g_src[E_MAX];
__device__ int    g_bsum[NB_MAX + 1];
__device__ int    g_is64;
__device__ int    g_swap;

// ---------------- probe: dtype of edge buffer + b/alpha order ----------------
__global__ void detect_kernel(const int* __restrict__ e,
                              const float* __restrict__ pb,
                              const float* __restrict__ pa) {
    int lane = threadIdx.x & 31;
    int nz = (e[2 * lane + 1] != 0) ? 1 : 0;     // odd words zero <=> int64
    unsigned m = __ballot_sync(0xFFFFFFFFu, nz);
    if (lane == 0) {
        g_is64 = (m == 0u) ? 1 : 0;
        g_swap = (pb[0] != 0.0f && pa[0] == 0.0f) ? 1 : 0;
    }
}

__device__ __forceinline__ int edge_val(const int* e, long long idx) {
    return g_is64 ? e[2 * idx] : e[(size_t)idx];
}

// ---------------- build CSR-by-destination ----------------
__global__ void zero_count_kernel(int n) {
    int i = blockIdx.x * blockDim.x + threadIdx.x;
    if (i < n) g_count[i] = 0;
}

__global__ void hist_kernel(const int* __restrict__ e, int E, int N) {
    int i = blockIdx.x * blockDim.x + threadIdx.x;
    if (i >= E) return;
    unsigned c = (unsigned)edge_val(e, (long long)E + i);
    if (c < (unsigned)N) atomicAdd(&g_count[c], 1);
}

__global__ __launch_bounds__(SCAN_B) void scanA_kernel(int N) {
    __shared__ int sm[SCAN_B];
    const int tid = threadIdx.x;
    const int i = blockIdx.x * SCAN_B + tid;
    int v = (i < N) ? g_count[i] : 0;
    sm[tid] = v;
    __syncthreads();
#pragma unroll
    for (int d = 1; d < SCAN_B; d <<= 1) {
        int t = sm[tid];
        int add = (tid >= d) ? sm[tid - d] : 0;
        __syncthreads();
        sm[tid] = t + add;
        __syncthreads();
    }
    if (i < N) g_off[i] = sm[tid] - v;
    if (tid == SCAN_B - 1) g_bsum[blockIdx.x] = sm[tid];
}

__global__ void scanB_kernel(int nb) {
    __shared__ int sm[128];
    const int tid = threadIdx.x;
    int v = (tid < nb) ? g_bsum[tid] : 0;
    sm[tid] = v;
    __syncthreads();
#pragma unroll
    for (int d = 1; d < 128; d <<= 1) {
        int t = sm[tid];
        int add = (tid >= d) ? sm[tid - d] : 0;
        __syncthreads();
        sm[tid] = t + add;
        __syncthreads();
    }
    if (tid < nb) g_bsum[tid] = sm[tid] - v;
}

__global__ void scanC_kernel(int N) {
    int i = blockIdx.x * blockDim.x + threadIdx.x;
    if (i >= N) return;
    int cnt = g_count[i];
    int off = g_off[i] + g_bsum[i >> 10];
    g_off[i] = off;
    g_cursor[i] = off;
    g_dinv[i] = rsqrtf((float)cnt + 1.0f);
    if (i == N - 1) g_off[N] = off + cnt;
}

__global__ void scatter_src_kernel(const int* __restrict__ e, int E, int N) {
    int i = blockIdx.x * blockDim.x + threadIdx.x;
    if (i >= E) return;
    unsigned r = (unsigned)edge_val(e, i);
    unsigned c = (unsigned)edge_val(e, (long long)E + i);
    if (r < (unsigned)N && c < (unsigned)N) {
        int p = atomicAdd(&g_cursor[c], 1);
        if ((unsigned)p < (unsigned)E) g_src[p] = (int)r;
    }
}

// ---------------- tf32 tensor-core GEMM: g_h = x @ W (fp16 out) ----------------
// CTA 128x128, 8 warps (4M x 2N), warp tile 32x64, k-slice 16, double buffer.
#define BM 128
#define BN 128
#define BKT 16
#define SMP (BM + 8)   // padded stride: bank = 8*tig + gid -> conflict-free

__device__ __forceinline__ uint32_t f2tf(float f) {
    uint32_t u;
    asm("cvt.rna.tf32.f32 %0, %1;" : "=r"(u) : "f"(f));
    return u;
}

__global__ __launch_bounds__(256) void gemm_tf32_kernel(const float* __restrict__ A,
                                                        const float* __restrict__ Bw,
                                                        int M) {
    __shared__ uint32_t As[2][BKT][SMP];   // [buf][k][m]
    __shared__ uint32_t Bs[2][BKT][SMP];   // [buf][k][n]
    const int tid = threadIdx.x;
    const int brow = blockIdx.x * BM;
    const int wid = tid >> 5;
    const int lane = tid & 31;
    const int gid = lane >> 2;       // 0..7
    const int tig = lane & 3;        // 0..3
    const int mrow0 = (wid & 3) * 32;
    const int ncol0 = (wid >> 2) * 64;

    float acc[2][8][4];
#pragma unroll
    for (int mt = 0; mt < 2; mt++)
#pragma unroll
        for (int nt = 0; nt < 8; nt++)
#pragma unroll
            for (int q = 0; q < 4; q++) acc[mt][nt][q] = 0.0f;

    // ---- stage slice 0 into buffer 0 ----
#pragma unroll
    for (int t = 0; t < 2; t++) {
        int v = tid + t * 256;
        int r = v >> 2;              // 0..127 (m)
        int kc = (v & 3) * 4;        // 0,4,8,12 (k)
        int grow = brow + r;
        float4 a = (grow < M) ? *(const float4*)(A + (size_t)grow * K_DIM + kc)
                              : make_float4(0.f, 0.f, 0.f, 0.f);
        As[0][kc + 0][r] = f2tf(a.x);
        As[0][kc + 1][r] = f2tf(a.y);
        As[0][kc + 2][r] = f2tf(a.z);
        As[0][kc + 3][r] = f2tf(a.w);
    }
#pragma unroll
    for (int t = 0; t < 2; t++) {
        int v = tid + t * 256;
        int r = v >> 5;              // 0..15 (k)
        int c = (v & 31) * 4;        // 0..124 (n)
        float4 b = *(const float4*)(Bw + (size_t)r * BN + c);
        Bs[0][r][c + 0] = f2tf(b.x);
        Bs[0][r][c + 1] = f2tf(b.y);
        Bs[0][r][c + 2] = f2tf(b.z);
        Bs[0][r][c + 3] = f2tf(b.w);
    }
    __syncthreads();

    const int NS = K_DIM / BKT;      // 16
    for (int kt = 0; kt < NS; kt++) {
        const int cur = kt & 1;
        const int nxt = cur ^ 1;

        // prefetch next slice into registers
        float4 pa[2], pb[2];
        if (kt + 1 < NS) {
            int kbase = (kt + 1) * BKT;
#pragma unroll
            for (int t = 0; t < 2; t++) {
                int v = tid + t * 256;
                int r = v >> 2;
                int kc = (v & 3) * 4;
                int grow = brow + r;
                pa[t] = (grow < M)
                    ? *(const float4*)(A + (size_t)grow * K_DIM + kbase + kc)
                    : make_float4(0.f, 0.f, 0.f, 0.f);
                int rb = v >> 5;
                int cb = (v & 31) * 4;
                pb[t] = *(const float4*)(Bw + (size_t)(kbase + rb) * BN + cb);
            }
        }

        // compute: two k8 halves of this 16-wide slice
#pragma unroll
        for (int kh = 0; kh < 2; kh++) {
            const int k0 = kh * 8;
            uint32_t bfr[8][2];
#pragma unroll
            for (int nt = 0; nt < 8; nt++) {
                bfr[nt][0] = Bs[cur][k0 + tig][ncol0 + nt * 8 + gid];
                bfr[nt][1] = Bs[cur][k0 + tig + 4][ncol0 + nt * 8 + gid];
            }
#pragma unroll
            for (int mt = 0; mt < 2; mt++) {
                const int mb = mrow0 + mt * 16;
                uint32_t a0 = As[cur][k0 + tig][mb + gid];
                uint32_t a1 = As[cur][k0 + tig][mb + gid + 8];
                uint32_t a2 = As[cur][k0 + tig + 4][mb + gid];
                uint32_t a3 = As[cur][k0 + tig + 4][mb + gid + 8];
#pragma unroll
                for (int nt = 0; nt < 8; nt++) {
                    asm volatile(
                        "mma.sync.aligned.m16n8k8.row.col.f32.tf32.tf32.f32 "
                        "{%0,%1,%2,%3}, {%4,%5,%6,%7}, {%8,%9}, {%0,%1,%2,%3};"
                        : "+f"(acc[mt][nt][0]), "+f"(acc[mt][nt][1]),
                          "+f"(acc[mt][nt][2]), "+f"(acc[mt][nt][3])
                        : "r"(a0), "r"(a1), "r"(a2), "r"(a3),
                          "r"(bfr[nt][0]), "r"(bfr[nt][1]));
                }
            }
        }

        if (kt + 1 < NS) {
            __syncthreads();   // all warps done computing before overwrite
#pragma unroll
            for (int t = 0; t < 2; t++) {
                int v = tid + t * 256;
                int r = v >> 2;
                int kc = (v & 3) * 4;
                As[nxt][kc + 0][r] = f2tf(pa[t].x);
                As[nxt][kc + 1][r] = f2tf(pa[t].y);
                As[nxt][kc + 2][r] = f2tf(pa[t].z);
                As[nxt][kc + 3][r] = f2tf(pa[t].w);
                int rb = v >> 5;
                int cb = (v & 31) * 4;
                Bs[nxt][rb][cb + 0] = f2tf(pb[t].x);
                Bs[nxt][rb][cb + 1] = f2tf(pb[t].y);
                Bs[nxt][rb][cb + 2] = f2tf(pb[t].z);
                Bs[nxt][rb][cb + 3] = f2tf(pb[t].w);
            }
            __syncthreads();   // stores visible before next iteration reads
        }
    }

    // ---- epilogue: convert to fp16, store ----
#pragma unroll
    for (int mt = 0; mt < 2; mt++) {
#pragma unroll
        for (int nt = 0; nt < 8; nt++) {
            int r0 = brow + mrow0 + mt * 16 + gid;
            int col = ncol0 + nt * 8 + 2 * tig;
            if (r0 < M) {
                __half2 p0 = __floats2half2_rn(acc[mt][nt][0], acc[mt][nt][1]);
                *(__half2*)(g_h + (size_t)r0 * H_DIM + col) = p0;
            }
            if (r0 + 8 < M) {
                __half2 p1 = __floats2half2_rn(acc[mt][nt][2], acc[mt][nt][3]);
                *(__half2*)(g_h + (size_t)(r0 + 8) * H_DIM + col) = p1;
            }
        }
    }
}

// ---------------- gather (fp16 messages) + per-src dinv + bias + PReLU -------
__device__ __forceinline__ void acc_half4(float4& acc, uint2 raw, float d) {
    __half2 h01 = *(__half2*)&raw.x;
    __half2 h23 = *(__half2*)&raw.y;
    float2 f01 = __half22float2(h01);
    float2 f23 = __half22float2(h23);
    acc.x = fmaf(f01.x, d, acc.x);
    acc.y = fmaf(f01.y, d, acc.y);
    acc.z = fmaf(f23.x, d, acc.z);
    acc.w = fmaf(f23.y, d, acc.w);
}

__global__ __launch_bounds__(256) void gather_kernel(const float* __restrict__ pb,
                                                     const float* __restrict__ pa,
                                                     float* __restrict__ out, int N) {
    int warp = (blockIdx.x * blockDim.x + threadIdx.x) >> 5;
    int lane = threadIdx.x & 31;
    if (warp >= N) return;
    const int c = warp;
    const float dc = g_dinv[c];
    const int s = g_off[c];
    const int e = g_off[c + 1];

    // self-loop: h[c] * dinv[c]   (whole sum gets * dc at the end)
    float4 acc = make_float4(0.f, 0.f, 0.f, 0.f);
    {
        uint2 raw = *(const uint2*)(g_h + (size_t)c * H_DIM + lane * 4);
        acc_half4(acc, raw, dc);
    }

    int i = s;
    for (; i + 3 < e; i += 4) {
        int s0 = g_src[i];
        int s1 = g_src[i + 1];
        int s2 = g_src[i + 2];
        int s3 = g_src[i + 3];
        float d0 = g_dinv[s0];
        float d1 = g_dinv[s1];
        float d2 = g_dinv[s2];
        float d3 = g_dinv[s3];
        uint2 v0 = *(const uint2*)(g_h + (size_t)s0 * H_DIM + lane * 4);
        uint2 v1 = *(const uint2*)(g_h + (size_t)s1 * H_DIM + lane * 4);
        uint2 v2 = *(const uint2*)(g_h + (size_t)s2 * H_DIM + lane * 4);
        uint2 v3 = *(const uint2*)(g_h + (size_t)s3 * H_DIM + lane * 4);
        acc_half4(acc, v0, d0);
        acc_half4(acc, v1, d1);
        acc_half4(acc, v2, d2);
        acc_half4(acc, v3, d3);
    }
    for (; i < e; i++) {
        int s0 = g_src[i];
        float d0 = g_dinv[s0];
        uint2 v0 = *(const uint2*)(g_h + (size_t)s0 * H_DIM + lane * 4);
        acc_half4(acc, v0, d0);
    }

    float4 bb = *(const float4*)(pb + lane * 4);
    float4 aa = *(const float4*)(pa + lane * 4);
    if (g_swap) { float4 t = bb; bb = aa; aa = t; }
    float4 r;
    float t;
    t = fmaf(acc.x, dc, bb.x); r.x = (t >= 0.f) ? t : aa.x * t;
    t = fmaf(acc.y, dc, bb.y); r.y = (t >= 0.f) ? t : aa.y * t;
    t = fmaf(acc.z, dc, bb.z); r.z = (t >= 0.f) ? t : aa.z * t;
    t = fmaf(acc.w, dc, bb.w); r.w = (t >= 0.f) ? t : aa.w * t;
    *(float4*)(out + (size_t)c * H_DIM + lane * 4) = r;
}

// ---------------- launch (fork-join: GEMM overlaps edge ingestion) ----------------
extern "C" void kernel_launch(void* const* d_in, const int* in_sizes, int n_in,
                              void* d_out, int out_size) {
    int ix = -1, ie = -1, iw = -1;
    for (int pass = 0; pass < 3; pass++) {
        int best = -1;
        long long bs = -1;
        for (int i = 0; i < n_in; i++) {
            if (i == ix || i == ie || i == iw) continue;
            if ((long long)in_sizes[i] > bs) { bs = in_sizes[i]; best = i; }
        }
        if (pass == 0) ix = best; else if (pass == 1) ie = best; else iw = best;
    }
    int ib = -1, ia = -1;
    for (int i = 0; i < n_in; i++) {
        if (i == ix || i == ie || i == iw) continue;
        if (ib < 0) ib = i; else ia = i;
    }

    const float* x = (const float*)d_in[ix];
    const int*   e = (const int*)d_in[ie];
    const float* W = (const float*)d_in[iw];
    const float* b = (const float*)d_in[ib];
    const float* alpha = (const float*)d_in[ia];
    float* out = (float*)d_out;

    const int N = in_sizes[ix] / K_DIM;   // 100000
    const int E = in_sizes[ie] / 2;       // 1600000
    const int NB = (N + SCAN_B - 1) / SCAN_B;
    const int TB = 256;

    static cudaStream_t s2 = nullptr;
    static cudaEvent_t evFork = nullptr, evJoin = nullptr;
    if (s2 == nullptr) {
        cudaStreamCreateWithFlags(&s2, cudaStreamNonBlocking);
        cudaEventCreateWithFlags(&evFork, cudaEventDisableTiming);
        cudaEventCreateWithFlags(&evJoin, cudaEventDisableTiming);
    }

    // fork: GEMM on s2 (depends on nothing device-side)
    cudaEventRecord(evFork, 0);
    cudaStreamWaitEvent(s2, evFork, 0);
    gemm_tf32_kernel<<<(N + BM - 1) / BM, 256, 0, s2>>>(x, W, N);
    cudaEventRecord(evJoin, s2);

    // edge ingestion chain on main stream
    detect_kernel<<<1, 32>>>(e, b, alpha);
    zero_count_kernel<<<(N + TB - 1) / TB, TB>>>(N);
    hist_kernel<<<(E + TB - 1) / TB, TB>>>(e, E, N);
    scanA_kernel<<<NB, SCAN_B>>>(N);
    scanB_kernel<<<1, 128>>>(NB);
    scanC_kernel<<<(N + TB - 1) / TB, TB>>>(N);
    scatter_src_kernel<<<(E + TB - 1) / TB, TB>>>(e, E, N);

    // join, then gather
    cudaStreamWaitEvent(0, evJoin, 0);
    gather_kernel<<<(int)(((long long)N * 32 + TB - 1) / TB), TB>>>(b, alpha, out, N);
}